// round 14
// baseline (speedup 1.0000x reference)
#include <cuda_runtime.h>

#define TT 300
#define NB 4

// f32-rounded versions of the reference's double constants
#define DCAY 0.8187307530779818f   // exp(-1/5)
#define PSPS 0.5436563656918091f   // e/5
#define REFS 1.3591409142295226f   // 2*1.25*e/5
#define THR  1.25f
#define PW   1.375f                // 1.1*theta (exact in f32)

#define KC 248                     // Eigen depth-panel size (ARM defaults)

typedef unsigned long long u64;

// ---- packed f32x2 helpers: per-lane rounding identical to scalar FFMA/FADD ----
__device__ __forceinline__ u64 pk2(float v){
    u64 r; asm("mov.b64 %0, {%1, %1};" : "=l"(r) : "f"(v)); return r;
}
__device__ __forceinline__ u64 fma2(u64 v, u64 w, u64 a){
    u64 r; asm("fma.rn.f32x2 %0, %1, %2, %3;" : "=l"(r) : "l"(v), "l"(w), "l"(a)); return r;
}
__device__ __forceinline__ u64 add2(u64 a, u64 b){
    u64 r; asm("add.rn.f32x2 %0, %1, %2;" : "=l"(r) : "l"(a), "l"(b)); return r;
}

// ---- scratch, time-major, CHANNEL-MINOR spatial layouts ----
__device__ float g_buf0[TT*8192];     // [t][4][32][32][2]
__device__ float g_buf1[TT*131072];   // [t][4][32][32][32]  conv1 raw
__device__ float g_buf2[TT*32768];    // [t][4][16][16][32]
__device__ float g_buf3[TT*65536];    // [t][4][16][16][64]  conv2 raw
__device__ float g_buf4[TT*16384];    // [t][4][8][8][64]
__device__ float g_buf5[TT*32768];    // [t][4][8][8][128]   conv3 raw
__device__ float g_buf6[TT*8192];     // [t][4][4][4][128]
__device__ float g_buf7[TT*1024];     // [t][4][256]
__device__ float g_buf8[TT*44];       // [t][4][11]

// weights transposed to [kh][kw][ci][oc] (HWIO): k-ascending == (kh,kw,ci), ci fastest
__device__ __align__(16) float g_w1t[50*32];
__device__ __align__(16) float g_w2t[288*64];
__device__ __align__(16) float g_w3t[576*128];
__device__ __align__(16) float g_w4at[2048*256];   // [k][o]

// ---------------- merged weight transpose (single launch) ----------------
__global__ void prep_all_k(const float* __restrict__ w1, const float* __restrict__ w2,
                           const float* __restrict__ w3, const float* __restrict__ w4a){
    int i = blockIdx.x*256 + threadIdx.x;
    if (i < 32*50){
        int o = i/50, rem = i%50;
        int c = rem/25, r = rem%25, kh = r/5, kw = r%5;
        g_w1t[((kh*5+kw)*2 + c)*32 + o] = w1[i];
    }
    if (i < 64*288){
        int o = i/288, rem = i%288;
        int ci = rem/9, r = rem%9, kh = r/3, kw = r%3;
        g_w2t[((kh*3+kw)*32 + ci)*64 + o] = w2[i];
    }
    if (i < 128*576){
        int o = i/576, rem = i%576;
        int ci = rem/9, r = rem%9, kh = r/3, kw = r%3;
        g_w3t[((kh*3+kw)*64 + ci)*128 + o] = w3[i];
    }
    if (i < 256*2048){
        int o = i/2048, k = i%2048;
        g_w4at[k*256+o] = w4a[i];
    }
}

// ---------------- stage 0: 4x4 sum-pool (binary inputs -> exact) ----------------
__global__ void pool0_kernel(const float* __restrict__ s){
    int t = blockIdx.x*32 + threadIdx.x;
    int n = blockIdx.y*blockDim.y + threadIdx.y;
    if (t >= TT) return;
    int c = n & 1, ow = (n>>1)&31, oh = (n>>6)&31, b = n>>11;
    const float* base = s + (size_t)(((b*2+c)*128 + oh*4)*128 + ow*4)*TT + t;
    float acc = 0.f;
    #pragma unroll
    for (int i=0;i<4;i++)
        #pragma unroll
        for (int j=0;j<4;j++)
            acc += base[(i*128+j)*TT];
    g_buf0[(size_t)t*8192 + n] = acc * PW;
}

// ---------------- fused PSP + refractory + threshold scan (strict rn) ----------
__global__ void scan_kernel(float* __restrict__ buf, int N){
    int n = blockIdx.x*blockDim.x + threadIdx.x;
    if (n >= N) return;
    float s1=0.f, s2=0.f, r1=0.f, r2=0.f;
    size_t idx = n;
    float a = buf[idx];
    #pragma unroll 2
    for (int t=0; t<TT; t++, idx += N){
        float nx = 0.f;
        if (t+1 < TT) nx = buf[idx + N];        // prefetch next step
        float x = a;
        s2 = __fmul_rn(DCAY, __fadd_rn(s2, s1));
        s1 = __fadd_rn(__fmul_rn(DCAY, s1), x);
        r2 = __fmul_rn(DCAY, __fadd_rn(r2, r1));
        r1 = __fmul_rn(DCAY, r1);
        float u = __fmul_rn(PSPS, s2);
        float v = __fsub_rn(__fsub_rn(u, __fmul_rn(REFS, r2)), THR);
        float spk = (v >= 0.f) ? 1.f : 0.f;
        r1 = __fadd_rn(r1, spk);
        buf[idx] = spk;
        a = nx;
    }
}

// ---------------- fused: scan(conv raw) -> 2x2 pool -> scan(pooled) ------------
template<int C, int Hin>
__global__ void scan2_pool_kernel(const float* __restrict__ in, float* __restrict__ out){
    const int Ho = Hin/2;
    const int Npool = 4*C*Ho*Ho;
    const int Tin = 4*C*Hin*Hin;
    int n = blockIdx.x*256 + threadIdx.x;
    int c = n & (C-1);
    int r = n / C;
    int ow = r % Ho; r /= Ho;
    int oh = r % Ho;
    int b = r / Ho;
    size_t base = ((size_t)(b*Hin + 2*oh)*Hin + 2*ow)*C + c;
    float S1[4]={0,0,0,0}, S2[4]={0,0,0,0}, R1[4]={0,0,0,0}, R2[4]={0,0,0,0};
    float ps1=0.f, ps2=0.f, pr1=0.f, pr2=0.f;
    const int off1 = C, off2 = Hin*C, off3 = Hin*C + C;
    const float* p = in + base;
    float a0=p[0], a1=p[off1], a2=p[off2], a3=p[off3];
    #pragma unroll 2
    for (int t=0; t<TT; t++){
        float b0=0.f,b1=0.f,b2=0.f,b3=0.f;
        if (t+1 < TT){                          // prefetch next step
            const float* pn = in + (size_t)(t+1)*Tin + base;
            b0=pn[0]; b1=pn[off1]; b2=pn[off2]; b3=pn[off3];
        }
        float xs[4] = {a0, a1, a2, a3};
        float sum = 0.f;
        #pragma unroll
        for (int j=0;j<4;j++){
            S2[j] = __fmul_rn(DCAY, __fadd_rn(S2[j], S1[j]));
            S1[j] = __fadd_rn(__fmul_rn(DCAY, S1[j]), xs[j]);
            R2[j] = __fmul_rn(DCAY, __fadd_rn(R2[j], R1[j]));
            R1[j] = __fmul_rn(DCAY, R1[j]);
            float u = __fmul_rn(PSPS, S2[j]);
            float v = __fsub_rn(__fsub_rn(u, __fmul_rn(REFS, R2[j])), THR);
            float spk = (v >= 0.f) ? 1.f : 0.f;
            R1[j] = __fadd_rn(R1[j], spk);
            sum += spk;                         // exact: small integers
        }
        float x = sum * PW;                     // exact
        ps2 = __fmul_rn(DCAY, __fadd_rn(ps2, ps1));
        ps1 = __fadd_rn(__fmul_rn(DCAY, ps1), x);
        pr2 = __fmul_rn(DCAY, __fadd_rn(pr2, pr1));
        pr1 = __fmul_rn(DCAY, pr1);
        float u = __fmul_rn(PSPS, ps2);
        float v = __fsub_rn(__fsub_rn(u, __fmul_rn(REFS, pr2)), THR);
        float spk = (v >= 0.f) ? 1.f : 0.f;
        pr1 = __fadd_rn(pr1, spk);
        out[(size_t)t*Npool + n] = spk;
        a0=b0; a1=b1; a2=b2; a3=b3;
    }
}

// ---------------- conv1: 2->32, 5x5 pad2, 32x32 --------------------------------
// block (32,8,2), 2 blocks/SM. Each thread: 2 row-groups x 2 og-subgroups of
// (2 px x 8 oc) sequentially -> only 8 u64 accumulators live.
__global__ void __launch_bounds__(512,2) conv1_kernel(){
    int tb = blockIdx.x; int b = tb & 3; int t = tb >> 2;
    __shared__ float tile[36*36*2];
    __shared__ __align__(16) float ws[50*32];
    int tx = threadIdx.x, ty = threadIdx.y, tz = threadIdx.z;
    int tid = (tz*8 + ty)*32 + tx;          // 0..511
    const float* inp = g_buf0 + (size_t)t*8192 + b*2048;
    for (int i = tid; i < 36*36*2; i += 512){
        int c = i & 1; int xy = i >> 1; int x = xy % 36; int y = xy / 36;
        int h = y-2, w = x-2;
        float v = 0.f;
        if ((unsigned)h < 32u && (unsigned)w < 32u) v = inp[(h*32+w)*2 + c];
        tile[i] = v;
    }
    for (int i = tid; i < 400; i += 512) ((float4*)ws)[i] = ((const float4*)g_w1t)[i];
    __syncthreads();
    int ox = tx;
    const u64* ws64 = (const u64*)ws;
    for (int s = 0; s < 2; s++){
        int oyA = ty + 16*s;                // pixel rows oyA, oyA+8
        for (int g = 0; g < 2; g++){        // oc base = tz*16 + g*8 -> u64 off tz*8+g*4
            int wo = tz*8 + g*4;
            u64 aA[4], aB[4];
            #pragma unroll
            for (int i=0;i<4;i++){ aA[i]=0ULL; aB[i]=0ULL; }
            for (int kh=0;kh<5;kh++)
                #pragma unroll
                for (int kw=0;kw<5;kw++){
                    float2 vA2 = *(const float2*)(tile + ((oyA+kh)*36 + ox+kw)*2);
                    float2 vB2 = *(const float2*)(tile + ((oyA+8+kh)*36 + ox+kw)*2);
                    u64 vA0=pk2(vA2.x), vA1=pk2(vA2.y), vB0=pk2(vB2.x), vB1=pk2(vB2.y);
                    const ulonglong2* w0 = (const ulonglong2*)(ws64 + ((kh*5+kw)*2+0)*16 + wo);
                    const ulonglong2* w1 = (const ulonglong2*)(ws64 + ((kh*5+kw)*2+1)*16 + wo);
                    #pragma unroll
                    for (int q=0;q<2;q++){
                        ulonglong2 wc0 = w0[q];
                        ulonglong2 wc1 = w1[q];
                        aA[2*q]   = fma2(vA0, wc0.x, aA[2*q]);
                        aA[2*q+1] = fma2(vA0, wc0.y, aA[2*q+1]);
                        aB[2*q]   = fma2(vB0, wc0.x, aB[2*q]);
                        aB[2*q+1] = fma2(vB0, wc0.y, aB[2*q+1]);
                        aA[2*q]   = fma2(vA1, wc1.x, aA[2*q]);
                        aA[2*q+1] = fma2(vA1, wc1.y, aA[2*q+1]);
                        aB[2*q]   = fma2(vB1, wc1.x, aB[2*q]);
                        aB[2*q+1] = fma2(vB1, wc1.y, aB[2*q+1]);
                    }
                }
            float2* opA = (float2*)(g_buf1 + (size_t)t*131072 + b*32768 + (oyA*32+ox)*32 + tz*16 + g*8);
            float2* opB = (float2*)(g_buf1 + (size_t)t*131072 + b*32768 + ((oyA+8)*32+ox)*32 + tz*16 + g*8);
            #pragma unroll
            for (int q=0;q<4;q++){ opA[q] = *reinterpret_cast<float2*>(&aA[q]);
                                   opB[q] = *reinterpret_cast<float2*>(&aB[q]); }
        }
    }
}

// ---------------- conv2: 32->64, 3x3 pad1, 16x16. K=288 = 248 + 40 ------------
// grid 2400: blockIdx&1 selects 32-oc half. block (16,8,4): 2 px x 8 oc/thread.
// smem = tile 40.5KB + weights 36.9KB = 77.4KB -> 2 blocks/SM.
extern __shared__ float s_dyn[];
__device__ __forceinline__ void c2_acc8(u64* aA, u64* aB, const float* trowA, const float* trowB,
                                        const u64* wci, int cp0, int cp1){
    for (int cp=cp0; cp<cp1; cp++){
        float2 vA2 = *(const float2*)(trowA + 2*cp);
        float2 vB2 = *(const float2*)(trowB + 2*cp);
        u64 vA0=pk2(vA2.x), vA1=pk2(vA2.y), vB0=pk2(vB2.x), vB1=pk2(vB2.y);
        const ulonglong2* w0 = (const ulonglong2*)(wci + (2*cp)*16);
        const ulonglong2* w1 = (const ulonglong2*)(wci + (2*cp+1)*16);
        #pragma unroll
        for (int q=0;q<2;q++){
            ulonglong2 wc0 = w0[q];
            ulonglong2 wc1 = w1[q];
            aA[2*q]   = fma2(vA0, wc0.x, aA[2*q]);
            aA[2*q+1] = fma2(vA0, wc0.y, aA[2*q+1]);
            aB[2*q]   = fma2(vB0, wc0.x, aB[2*q]);
            aB[2*q+1] = fma2(vB0, wc0.y, aB[2*q+1]);
            aA[2*q]   = fma2(vA1, wc1.x, aA[2*q]);
            aA[2*q+1] = fma2(vA1, wc1.y, aA[2*q+1]);
            aB[2*q]   = fma2(vB1, wc1.x, aB[2*q]);
            aB[2*q+1] = fma2(vB1, wc1.y, aB[2*q+1]);
        }
    }
}
__global__ void __launch_bounds__(512,2) conv2_kernel(){
    int bb = blockIdx.x; int half = bb & 1; int tb = bb >> 1;
    int b = tb & 3; int t = tb >> 2;
    float* tile = s_dyn;                    // [18][18][32]  10368 f
    float* wsm  = s_dyn + 10368;            // [9 tap][32 ci][32 oc-half] 9216 f
    int tx = threadIdx.x, ty = threadIdx.y, tz = threadIdx.z;  // (16,8,4)
    int tid = (tz*8 + ty)*16 + tx;                              // 0..511
    const float* inp = g_buf2 + (size_t)t*32768 + b*8192;
    for (int i = tid; i < 10368; i += 512){
        int c = i & 31; int xy = i >> 5; int x = xy % 18; int y = xy / 18;
        int h = y-1, w = x-1;
        float v = 0.f;
        if ((unsigned)h < 16u && (unsigned)w < 16u) v = inp[(h*16+w)*32 + c];
        tile[i] = v;
    }
    for (int i = tid; i < 2304; i += 512){          // 9*32 rows x 8 float4
        int f4 = i & 7; int row = i >> 3;           // row = tap*32+ci
        ((float4*)wsm)[row*8 + f4] = ((const float4*)g_w2t)[row*16 + half*8 + f4];
    }
    __syncthreads();
    int ox = tx, og = tz;                           // oc = half*32 + og*8
    const u64* wsm64 = (const u64*)wsm;
    u64 aA[4], aB[4], tA[4], tB[4];
    #pragma unroll
    for (int i=0;i<4;i++){ aA[i]=0ULL; aB[i]=0ULL; }
    // panel A: taps 0..6 full, tap7 cp<12 (ci<24)
    for (int tap=0; tap<7; tap++){
        const float* trowA = tile + ((ty + tap/3)*18 + ox + tap%3)*32;
        const float* trowB = trowA + 8*18*32;
        c2_acc8(aA, aB, trowA, trowB, wsm64 + tap*512 + og*4, 0, 16);
    }
    const float* trowA7 = tile + ((ty+2)*18 + ox+1)*32;
    const float* trowB7 = trowA7 + 8*18*32;
    c2_acc8(aA, aB, trowA7, trowB7, wsm64 + 7*512 + og*4, 0, 12);
    #pragma unroll
    for (int i=0;i<4;i++){ tA[i]=aA[i]; tB[i]=aB[i]; aA[i]=0ULL; aB[i]=0ULL; }
    // panel B: tap7 cp>=12, tap8 full
    c2_acc8(aA, aB, trowA7, trowB7, wsm64 + 7*512 + og*4, 12, 16);
    const float* trowA8 = tile + ((ty+2)*18 + ox+2)*32;
    const float* trowB8 = trowA8 + 8*18*32;
    c2_acc8(aA, aB, trowA8, trowB8, wsm64 + 8*512 + og*4, 0, 16);
    #pragma unroll
    for (int i=0;i<4;i++){ tA[i] = add2(tA[i], aA[i]); tB[i] = add2(tB[i], aB[i]); }
    float2* opA = (float2*)(g_buf3 + (size_t)t*65536 + b*16384 + (ty*16+ox)*64 + half*32 + og*8);
    float2* opB = (float2*)(g_buf3 + (size_t)t*65536 + b*16384 + ((ty+8)*16+ox)*64 + half*32 + og*8);
    #pragma unroll
    for (int q=0;q<4;q++){ opA[q] = *reinterpret_cast<float2*>(&tA[q]);
                           opB[q] = *reinterpret_cast<float2*>(&tB[q]); }
}

// ---------------- conv3: 64->128, 3x3 pad1, 8x8. K=576 = 248+248+80 -----------
// grid 2400: blockIdx&1 selects 64-oc half. block (8,4,16): 2 px x 4 oc/thread.
// smem = tile 25KB + per-kh weights 48KB = 73KB -> 2 blocks/SM.
__device__ __forceinline__ void c3_acc4(u64* aA, u64* aB, const float* trowA, const float* trowB,
                                        const u64* wci, int cp0, int cp1){
    for (int cp=cp0; cp<cp1; cp++){
        float2 vA2 = *(const float2*)(trowA + 2*cp);
        float2 vB2 = *(const float2*)(trowB + 2*cp);
        u64 vA0=pk2(vA2.x), vA1=pk2(vA2.y), vB0=pk2(vB2.x), vB1=pk2(vB2.y);
        ulonglong2 wc0 = *(const ulonglong2*)(wci + (2*cp)*32);
        ulonglong2 wc1 = *(const ulonglong2*)(wci + (2*cp+1)*32);
        aA[0] = fma2(vA0, wc0.x, aA[0]);
        aA[1] = fma2(vA0, wc0.y, aA[1]);
        aB[0] = fma2(vB0, wc0.x, aB[0]);
        aB[1] = fma2(vB0, wc0.y, aB[1]);
        aA[0] = fma2(vA1, wc1.x, aA[0]);
        aA[1] = fma2(vA1, wc1.y, aA[1]);
        aB[0] = fma2(vB1, wc1.x, aB[0]);
        aB[1] = fma2(vB1, wc1.y, aB[1]);
    }
}
__global__ void __launch_bounds__(512,2) conv3_kernel(){
    int bb = blockIdx.x; int half = bb & 1; int tb = bb >> 1;
    int b = tb & 3; int t = tb >> 2;
    float* tile = s_dyn;            // [10][10][64]  6400 f
    float* wsm  = s_dyn + 6400;     // per-kh [3 kw][64 ci][64 oc-half] 12288 f
    int tx = threadIdx.x, ty = threadIdx.y, tz = threadIdx.z;  // (8,4,16)
    int tid = (tz*4 + ty)*8 + tx;                               // 0..511
    const float* inp = g_buf4 + (size_t)t*16384 + b*4096;
    for (int i = tid; i < 6400; i += 512){
        int c = i & 63; int xy = i >> 6; int x = xy % 10; int y = xy / 10;
        int h = y-1, w = x-1;
        float v = 0.f;
        if ((unsigned)h < 8u && (unsigned)w < 8u) v = inp[(h*8+w)*64 + c];
        tile[i] = v;
    }
    int ox = tx, og = tz;           // oc = half*64 + og*4 -> u64 offset og*2
    u64 aA[2], aB[2], tA[2], tB[2];
    #pragma unroll
    for (int i=0;i<2;i++){ aA[i]=0ULL; aB[i]=0ULL; tA[i]=0ULL; tB[i]=0ULL; }
    for (int kh=0; kh<3; kh++){
        __syncthreads();
        for (int i = tid; i < 3072; i += 512){      // 3*64 rows x 16 float4 (half)
            int f4 = i & 15; int row = i >> 4;      // row = kw*64+ci
            ((float4*)wsm)[row*16 + f4] =
                ((const float4*)g_w3t)[(kh*192 + row)*32 + half*16 + f4];
        }
        __syncthreads();
        const u64* wsm64 = (const u64*)wsm;
        const float* rA = tile + (ty+kh)*10*64;
        const float* rB = tile + (ty+4+kh)*10*64;
        if (kh == 0){
            #pragma unroll
            for (int kw=0;kw<3;kw++)
                c3_acc4(aA, aB, rA + (ox+kw)*64, rB + (ox+kw)*64, wsm64 + kw*2048 + og*2, 0, 32);
        } else if (kh == 1){
            c3_acc4(aA, aB, rA + ox*64, rB + ox*64, wsm64 + 0*2048 + og*2, 0, 28);
            #pragma unroll
            for (int i=0;i<2;i++){ tA[i]=add2(tA[i],aA[i]); tB[i]=add2(tB[i],aB[i]); aA[i]=0ULL; aB[i]=0ULL; }
            c3_acc4(aA, aB, rA + ox*64, rB + ox*64, wsm64 + 0*2048 + og*2, 28, 32);
            #pragma unroll
            for (int kw=1;kw<3;kw++)
                c3_acc4(aA, aB, rA + (ox+kw)*64, rB + (ox+kw)*64, wsm64 + kw*2048 + og*2, 0, 32);
        } else {
            c3_acc4(aA, aB, rA + ox*64, rB + ox*64, wsm64 + 0*2048 + og*2, 0, 32);
            c3_acc4(aA, aB, rA + (ox+1)*64, rB + (ox+1)*64, wsm64 + 1*2048 + og*2, 0, 24);
            #pragma unroll
            for (int i=0;i<2;i++){ tA[i]=add2(tA[i],aA[i]); tB[i]=add2(tB[i],aB[i]); aA[i]=0ULL; aB[i]=0ULL; }
            c3_acc4(aA, aB, rA + (ox+1)*64, rB + (ox+1)*64, wsm64 + 1*2048 + og*2, 24, 32);
            c3_acc4(aA, aB, rA + (ox+2)*64, rB + (ox+2)*64, wsm64 + 2*2048 + og*2, 0, 32);
        }
    }
    #pragma unroll
    for (int i=0;i<2;i++){ tA[i]=add2(tA[i],aA[i]); tB[i]=add2(tB[i],aB[i]); }
    float2* opA = (float2*)(g_buf5 + (size_t)t*32768 + b*8192 + (ty*8+ox)*128 + half*64 + og*4);
    float2* opB = (float2*)(g_buf5 + (size_t)t*32768 + b*8192 + ((ty+4)*8+ox)*128 + half*64 + og*4);
    #pragma unroll
    for (int q=0;q<2;q++){ opA[q] = *reinterpret_cast<float2*>(&tA[q]);
                           opB[q] = *reinterpret_cast<float2*>(&tB[q]); }
}

// ---------------- dense1: 2048 -> 256. K = 8x248 + 64 panels -------------------
__global__ void dense1_kernel(){
    __shared__ float xs[8][KC];
    int row0 = blockIdx.x*8;
    int o = threadIdx.x;
    float acc[8], tot[8];
    #pragma unroll
    for (int r=0;r<8;r++){ acc[r]=0.f; tot[r]=0.f; }
    int k0 = 0;
    for (int p=0; p<9; p++){
        int L = (p<8) ? KC : (2048 - 8*KC);
        __syncthreads();
        for (int i=threadIdx.x; i<8*L; i+=256){
            int r = i / L, kk = i - r*L;
            int k = k0 + kk;
            int c = k >> 4, hw = k & 15;
            xs[r][kk] = g_buf6[(size_t)(row0+r)*2048 + hw*128 + c];
        }
        __syncthreads();
        for (int kk=0; kk<L; kk++){
            float wv = g_w4at[(size_t)(k0+kk)*256 + o];
            #pragma unroll
            for (int r=0;r<8;r++) acc[r] = __fmaf_rn(xs[r][kk], wv, acc[r]);
        }
        #pragma unroll
        for (int r=0;r<8;r++){ tot[r] = __fadd_rn(tot[r], acc[r]); acc[r]=0.f; }
        k0 += L;
    }
    for (int r=0;r<8;r++) g_buf7[(size_t)(row0+r)*256 + o] = tot[r];
}

// ---------------- dense2: 256 -> 11. K = 248 + 8 panels ------------------------
__global__ void dense2_kernel(const float* __restrict__ w4b){
    int tb = blockIdx.x;
    __shared__ float xs[256];
    int tid = threadIdx.x;
    for (int i=tid;i<256;i+=64) xs[i] = g_buf7[(size_t)tb*256 + i];
    __syncthreads();
    if (tid < 11){
        float acc = 0.f;
        for (int k=0;k<KC;k++)  acc = __fmaf_rn(xs[k], w4b[tid*256+k], acc);
        float tot = acc; acc = 0.f;
        for (int k=KC;k<256;k++) acc = __fmaf_rn(xs[k], w4b[tid*256+k], acc);
        tot = __fadd_rn(tot, acc);
        int t = tb >> 2, b = tb & 3;
        g_buf8[t*44 + b*11 + tid] = tot;
    }
}

// ---------------- final scan, output layout [b][o][t] --------------------------
__global__ void scan_out_kernel(float* __restrict__ out){
    int n = threadIdx.x;
    if (n >= 44) return;
    int b = n/11, o = n - b*11;
    float s1=0.f, s2=0.f, r1=0.f, r2=0.f;
    #pragma unroll 4
    for (int t=0;t<TT;t++){
        float x = g_buf8[t*44 + n];
        s2 = __fmul_rn(DCAY, __fadd_rn(s2, s1));
        s1 = __fadd_rn(__fmul_rn(DCAY, s1), x);
        r2 = __fmul_rn(DCAY, __fadd_rn(r2, r1));
        r1 = __fmul_rn(DCAY, r1);
        float u = __fmul_rn(PSPS, s2);
        float v = __fsub_rn(__fsub_rn(u, __fmul_rn(REFS, r2)), THR);
        float spk = (v >= 0.f) ? 1.f : 0.f;
        r1 = __fadd_rn(r1, spk);
        out[(size_t)(b*11+o)*TT + t] = spk;
    }
}

extern "C" void kernel_launch(void* const* d_in, const int* in_sizes, int n_in,
                              void* d_out, int out_size){
    const float* s_in = (const float*)d_in[0];
    const float* w1   = (const float*)d_in[1];
    const float* w2   = (const float*)d_in[2];
    const float* w3   = (const float*)d_in[3];
    const float* w4a  = (const float*)d_in[4];
    const float* w4b  = (const float*)d_in[5];
    float* out = (float*)d_out;

    float *b0,*b1,*b2,*b3,*b4,*b5,*b6,*b7;
    cudaGetSymbolAddress((void**)&b0, g_buf0);
    cudaGetSymbolAddress((void**)&b1, g_buf1);
    cudaGetSymbolAddress((void**)&b2, g_buf2);
    cudaGetSymbolAddress((void**)&b3, g_buf3);
    cudaGetSymbolAddress((void**)&b4, g_buf4);
    cudaGetSymbolAddress((void**)&b5, g_buf5);
    cudaGetSymbolAddress((void**)&b6, g_buf6);
    cudaGetSymbolAddress((void**)&b7, g_buf7);

    static bool attr_done = false;
    if (!attr_done){
        cudaFuncSetAttribute(conv2_kernel, cudaFuncAttributeMaxDynamicSharedMemorySize, 78336);
        cudaFuncSetAttribute(conv3_kernel, cudaFuncAttributeMaxDynamicSharedMemorySize, 74752);
        attr_done = true;
    }

    prep_all_k<<<2048,256>>>(w1, w2, w3, w4a);

    pool0_kernel<<<dim3(10,1024), dim3(32,8)>>>(s_in);
    scan_kernel<<<32,256>>>(b0, 8192);

    conv1_kernel<<<1200, dim3(32,8,2)>>>();
    scan2_pool_kernel<32,32><<<128,256>>>(b1, b2);

    conv2_kernel<<<2400, dim3(16,8,4), 78336>>>();
    scan2_pool_kernel<64,16><<<64,256>>>(b3, b4);

    conv3_kernel<<<2400, dim3(8,4,16), 74752>>>();
    scan2_pool_kernel<128,8><<<32,256>>>(b5, b6);

    dense1_kernel<<<150,256>>>();
    scan_kernel<<<4,256>>>(b7, 1024);

    dense2_kernel<<<1200,64>>>(w4b);
    scan_out_kernel<<<1,64>>>(out);
}

// round 15
// speedup vs baseline: 1.5795x; 1.5795x over previous
#include <cuda_runtime.h>

#define TT 300
#define NB 4

// f32-rounded versions of the reference's double constants
#define DCAY 0.8187307530779818f   // exp(-1/5)
#define PSPS 0.5436563656918091f   // e/5
#define REFS 1.3591409142295226f   // 2*1.25*e/5
#define THR  1.25f
#define PW   1.375f                // 1.1*theta (exact in f32)

#define KC 248                     // Eigen depth-panel size (ARM defaults)

typedef unsigned long long u64;

// add.rn.f32x2: per-lane rounding identical to scalar FADD
__device__ __forceinline__ u64 add2(u64 a, u64 b){
    u64 r; asm("add.rn.f32x2 %0, %1, %2;" : "=l"(r) : "l"(a), "l"(b)); return r;
}

// ---- scratch, time-major, CHANNEL-MINOR spatial layouts ----
__device__ float g_buf0[TT*8192];     // [t][4][32][32][2]
__device__ float g_buf1[TT*131072];   // [t][4][32][32][32]  conv1 raw
__device__ float g_buf2[TT*32768];    // [t][4][16][16][32]
__device__ float g_buf3[TT*65536];    // [t][4][16][16][64]  conv2 raw
__device__ float g_buf4[TT*16384];    // [t][4][8][8][64]
__device__ float g_buf5[TT*32768];    // [t][4][8][8][128]   conv3 raw
__device__ float g_buf6[TT*8192];     // [t][4][4][4][128]
__device__ float g_buf7[TT*1024];     // [t][4][256]
__device__ float g_buf8[TT*44];       // [t][4][11]

// weights transposed to [kh][kw][ci][oc] (HWIO): k-ascending == (kh,kw,ci), ci fastest
__device__ __align__(16) float g_w1t[50*32];
__device__ __align__(16) float g_w2t[288*64];
__device__ __align__(16) float g_w3t[576*128];
__device__ __align__(16) float g_w4at[2048*256];   // [k][o]

// ---------------- merged weight transpose (single launch) ----------------
__global__ void prep_all_k(const float* __restrict__ w1, const float* __restrict__ w2,
                           const float* __restrict__ w3, const float* __restrict__ w4a){
    int i = blockIdx.x*256 + threadIdx.x;
    if (i < 32*50){
        int o = i/50, rem = i%50;
        int c = rem/25, r = rem%25, kh = r/5, kw = r%5;
        g_w1t[((kh*5+kw)*2 + c)*32 + o] = w1[i];
    }
    if (i < 64*288){
        int o = i/288, rem = i%288;
        int ci = rem/9, r = rem%9, kh = r/3, kw = r%3;
        g_w2t[((kh*3+kw)*32 + ci)*64 + o] = w2[i];
    }
    if (i < 128*576){
        int o = i/576, rem = i%576;
        int ci = rem/9, r = rem%9, kh = r/3, kw = r%3;
        g_w3t[((kh*3+kw)*64 + ci)*128 + o] = w3[i];
    }
    if (i < 256*2048){
        int o = i/2048, k = i%2048;
        g_w4at[k*256+o] = w4a[i];
    }
}

// ---------------- stage 0: 4x4 sum-pool (binary inputs -> exact) ----------------
__global__ void pool0_kernel(const float* __restrict__ s){
    int t = blockIdx.x*32 + threadIdx.x;
    int n = blockIdx.y*blockDim.y + threadIdx.y;
    if (t >= TT) return;
    int c = n & 1, ow = (n>>1)&31, oh = (n>>6)&31, b = n>>11;
    const float* base = s + (size_t)(((b*2+c)*128 + oh*4)*128 + ow*4)*TT + t;
    float acc = 0.f;
    #pragma unroll
    for (int i=0;i<4;i++)
        #pragma unroll
        for (int j=0;j<4;j++)
            acc += base[(i*128+j)*TT];
    g_buf0[(size_t)t*8192 + n] = acc * PW;
}

// ---------------- fused PSP + refractory + threshold scan (strict rn) ----------
// depth-3 prefetch: loads are scan-state-independent.
__global__ void scan_kernel(float* __restrict__ buf, int N){
    int n = blockIdx.x*blockDim.x + threadIdx.x;
    if (n >= N) return;
    float s1=0.f, s2=0.f, r1=0.f, r2=0.f;
    float pf[3];
    pf[0] = buf[n];
    pf[1] = buf[n + (size_t)N];
    pf[2] = buf[n + 2*(size_t)N];
    size_t idx = n;
    #pragma unroll 3
    for (int t=0; t<TT; t++, idx += N){
        int slot = t % 3;
        float x = pf[slot];
        pf[slot] = (t+3 < TT) ? buf[idx + 3*(size_t)N] : 0.f;
        s2 = __fmul_rn(DCAY, __fadd_rn(s2, s1));
        s1 = __fadd_rn(__fmul_rn(DCAY, s1), x);
        r2 = __fmul_rn(DCAY, __fadd_rn(r2, r1));
        r1 = __fmul_rn(DCAY, r1);
        float u = __fmul_rn(PSPS, s2);
        float v = __fsub_rn(__fsub_rn(u, __fmul_rn(REFS, r2)), THR);
        float spk = (v >= 0.f) ? 1.f : 0.f;
        r1 = __fadd_rn(r1, spk);
        buf[idx] = spk;
    }
}

// ---------------- fused: scan(conv raw) -> 2x2 pool -> scan(pooled) ------------
// Bit-identical to scan + pool + scan chain. depth-3 prefetch.
template<int C, int Hin>
__global__ void scan2_pool_kernel(const float* __restrict__ in, float* __restrict__ out){
    const int Ho = Hin/2;
    const int Npool = 4*C*Ho*Ho;
    const int Tin = 4*C*Hin*Hin;
    int n = blockIdx.x*256 + threadIdx.x;
    int c = n & (C-1);
    int r = n / C;
    int ow = r % Ho; r /= Ho;
    int oh = r % Ho;
    int b = r / Ho;
    size_t base = ((size_t)(b*Hin + 2*oh)*Hin + 2*ow)*C + c;
    float S1[4]={0,0,0,0}, S2[4]={0,0,0,0}, R1[4]={0,0,0,0}, R2[4]={0,0,0,0};
    float ps1=0.f, ps2=0.f, pr1=0.f, pr2=0.f;
    const int off1 = C, off2 = Hin*C, off3 = Hin*C + C;
    float pf[3][4];
    #pragma unroll
    for (int d=0;d<3;d++){
        const float* p = in + (size_t)d*Tin + base;
        pf[d][0]=p[0]; pf[d][1]=p[off1]; pf[d][2]=p[off2]; pf[d][3]=p[off3];
    }
    #pragma unroll 3
    for (int t=0; t<TT; t++){
        int slot = t % 3;
        float xs[4] = {pf[slot][0], pf[slot][1], pf[slot][2], pf[slot][3]};
        if (t+3 < TT){
            const float* pn = in + (size_t)(t+3)*Tin + base;
            pf[slot][0]=pn[0]; pf[slot][1]=pn[off1]; pf[slot][2]=pn[off2]; pf[slot][3]=pn[off3];
        }
        float sum = 0.f;
        #pragma unroll
        for (int j=0;j<4;j++){
            S2[j] = __fmul_rn(DCAY, __fadd_rn(S2[j], S1[j]));
            S1[j] = __fadd_rn(__fmul_rn(DCAY, S1[j]), xs[j]);
            R2[j] = __fmul_rn(DCAY, __fadd_rn(R2[j], R1[j]));
            R1[j] = __fmul_rn(DCAY, R1[j]);
            float u = __fmul_rn(PSPS, S2[j]);
            float v = __fsub_rn(__fsub_rn(u, __fmul_rn(REFS, R2[j])), THR);
            float spk = (v >= 0.f) ? 1.f : 0.f;
            R1[j] = __fadd_rn(R1[j], spk);
            sum += spk;                         // exact: small integers
        }
        float x = sum * PW;                     // exact
        ps2 = __fmul_rn(DCAY, __fadd_rn(ps2, ps1));
        ps1 = __fadd_rn(__fmul_rn(DCAY, ps1), x);
        pr2 = __fmul_rn(DCAY, __fadd_rn(pr2, pr1));
        pr1 = __fmul_rn(DCAY, pr1);
        float u = __fmul_rn(PSPS, ps2);
        float v = __fsub_rn(__fsub_rn(u, __fmul_rn(REFS, pr2)), THR);
        float spk = (v >= 0.f) ? 1.f : 0.f;
        pr1 = __fadd_rn(pr1, spk);
        out[(size_t)t*Npool + n] = spk;
    }
}

// ================= SPARSE CONVS =================
// All conv inputs are binary spikes. fma(0,w,acc)=acc and fma(1,w,acc)=fadd(acc,w)
// bit-exactly, so summing weight rows over active taps in the same ascending
// k-order with the same panel splits reproduces the dense chain bit-for-bit.
// One warp per pixel: activity mask is warp-uniform -> no divergence.

// ---------------- conv1: 2->32, 5x5 pad2, 32x32. K=50, single panel -----------
__global__ void __launch_bounds__(512,2) conv1_kernel(){
    int tb = blockIdx.x; int b = tb & 3; int t = tb >> 2;
    __shared__ unsigned msk[36*36];
    __shared__ float ws[50*32];
    int tid = threadIdx.x; int lane = tid & 31; int warp = tid >> 5;  // 16 warps
    const float* inp = g_buf0 + (size_t)t*8192 + b*2048;
    for (int i = tid; i < 400; i += 512) ((float4*)ws)[i] = ((const float4*)g_w1t)[i];
    for (int i = tid; i < 1296; i += 512){
        int x = i % 36, y = i / 36;
        int h = y-2, w = x-2;
        unsigned m = 0;
        if ((unsigned)h < 32u && (unsigned)w < 32u){
            const float* p = inp + (h*32+w)*2;
            m = (p[0] != 0.f ? 1u : 0u) | (p[1] != 0.f ? 2u : 0u);
        }
        msk[i] = m;
    }
    __syncthreads();
    float* op = g_buf1 + (size_t)t*131072 + b*32768;
    for (int i = 0; i < 64; i++){
        int px = warp*64 + i;
        int ox = px & 31, oy = px >> 5;
        float acc = 0.f;
        #pragma unroll
        for (int kh=0;kh<5;kh++)
            #pragma unroll
            for (int kw=0;kw<5;kw++){
                unsigned m = msk[(oy+kh)*36 + ox+kw];
                int tap = kh*5+kw;
                if (m & 1u) acc = __fadd_rn(acc, ws[(tap*2+0)*32 + lane]);
                if (m & 2u) acc = __fadd_rn(acc, ws[(tap*2+1)*32 + lane]);
            }
        op[px*32 + lane] = acc;
    }
}

// ---------------- conv2: 32->64, 3x3 pad1, 16x16. K=288 = 248 + 40 ------------
// Panel boundary k=248 -> tap7 ci24. Lane owns oc pair {2l,2l+1} (1 u64).
extern __shared__ float s_dyn[];
__global__ void __launch_bounds__(512,2) conv2_kernel(){
    int tb = blockIdx.x; int b = tb & 3; int t = tb >> 2;
    u64* wsm = (u64*)s_dyn;                          // [288 rows][32 u64] = 73728 B
    unsigned* msk = (unsigned*)(s_dyn + 18432);      // 324 u32
    int tid = threadIdx.x; int lane = tid & 31; int warp = tid >> 5;
    const float* inp = g_buf2 + (size_t)t*32768 + b*8192;
    for (int i = tid; i < 4608; i += 512) ((float4*)wsm)[i] = ((const float4*)g_w2t)[i];
    for (int pos = warp; pos < 324; pos += 16){
        int x = pos % 18, y = pos / 18, h = y-1, w = x-1;
        float v = 0.f;
        if ((unsigned)h < 16u && (unsigned)w < 16u) v = inp[(h*16+w)*32 + lane];
        unsigned m = __ballot_sync(0xffffffffu, v != 0.f);
        if (lane == 0) msk[pos] = m;
    }
    __syncthreads();
    float2* opb = (float2*)(g_buf3 + (size_t)t*65536 + b*16384);
    for (int i = 0; i < 16; i++){
        int px = warp*16 + i;
        int ox = px & 15, oy = px >> 4;
        u64 acc = 0ULL;
        // panel A: taps 0..6 full + tap7 ci<24
        #pragma unroll
        for (int tap=0; tap<7; tap++){
            unsigned m = msk[(oy + tap/3)*18 + ox + tap%3];
            const u64* wrow = wsm + tap*1024;
            while (m){ int ci = __ffs(m)-1; m &= m-1;
                       acc = add2(acc, wrow[ci*32 + lane]); }
        }
        unsigned m7 = msk[(oy+2)*18 + ox+1];
        {   unsigned m = m7 & 0x00FFFFFFu;
            const u64* wrow = wsm + 7*1024;
            while (m){ int ci = __ffs(m)-1; m &= m-1;
                       acc = add2(acc, wrow[ci*32 + lane]); }
        }
        u64 tot = acc; acc = 0ULL;
        // panel B: tap7 ci>=24 + tap8 full
        {   unsigned m = m7 & 0xFF000000u;
            const u64* wrow = wsm + 7*1024;
            while (m){ int ci = __ffs(m)-1; m &= m-1;
                       acc = add2(acc, wrow[ci*32 + lane]); }
        }
        {   unsigned m = msk[(oy+2)*18 + ox+2];
            const u64* wrow = wsm + 8*1024;
            while (m){ int ci = __ffs(m)-1; m &= m-1;
                       acc = add2(acc, wrow[ci*32 + lane]); }
        }
        acc = add2(tot, acc);                    // single panel-combine fadd
        opb[px*32 + lane] = *reinterpret_cast<float2*>(&acc);
    }
}

// ---------------- conv3: 64->128, 3x3 pad1, 8x8. K=576 = 248+248+80 -----------
// Boundaries: k=248 (tap3 ci56), k=496 (tap7 ci48). Lane owns oc {4l..4l+3}
// (ulonglong2). Weights staged per kh (98.3 KB); 4 px per warp, accs persist.
__device__ __forceinline__ void c3_run(ulonglong2& acc, const u64* wsm,
                                       int kw, unsigned m, int cibase, int lane){
    const u64* wrow0 = wsm + kw*4096 + 2*lane;
    while (m){
        int bit = __ffs(m)-1; m &= m-1;
        const ulonglong2 w = *(const ulonglong2*)(wrow0 + (cibase + bit)*64);
        acc.x = add2(acc.x, w.x);
        acc.y = add2(acc.y, w.y);
    }
}
__global__ void __launch_bounds__(512,2) conv3_kernel(){
    int tb = blockIdx.x; int b = tb & 3; int t = tb >> 2;
    u64* wsm = (u64*)s_dyn;                          // per-kh [3 kw][64 ci][64 u64] = 98304 B
    unsigned* msk = (unsigned*)(s_dyn + 24576);      // [100][2] u32
    int tid = threadIdx.x; int lane = tid & 31; int warp = tid >> 5;
    const float* inp = g_buf4 + (size_t)t*16384 + b*4096;
    for (int pos = warp; pos < 100; pos += 16){
        int x = pos % 10, y = pos / 10, h = y-1, w = x-1;
        float v0 = 0.f, v1 = 0.f;
        if ((unsigned)h < 8u && (unsigned)w < 8u){
            const float* p = inp + (h*8+w)*64;
            v0 = p[lane]; v1 = p[32 + lane];
        }
        unsigned m0 = __ballot_sync(0xffffffffu, v0 != 0.f);
        unsigned m1 = __ballot_sync(0xffffffffu, v1 != 0.f);
        if (lane == 0){ msk[pos*2] = m0; msk[pos*2+1] = m1; }
    }
    ulonglong2 acc[4], tot[4];
    #pragma unroll
    for (int i=0;i<4;i++){ acc[i] = make_ulonglong2(0ULL,0ULL); tot[i] = make_ulonglong2(0ULL,0ULL); }
    for (int kh=0; kh<3; kh++){
        __syncthreads();
        for (int i = tid; i < 6144; i += 512){       // 192 rows x 32 float4
            int f4 = i & 31; int row = i >> 5;
            ((float4*)wsm)[i] = ((const float4*)g_w3t)[(kh*192 + row)*32 + f4];
        }
        __syncthreads();
        #pragma unroll
        for (int i=0;i<4;i++){
            int px = warp*4 + i;
            int ox = px & 7, oy = px >> 3;
            #pragma unroll
            for (int kw=0;kw<3;kw++){
                int pos = ((oy+kh)*10 + ox+kw)*2;
                unsigned m0 = msk[pos], m1 = msk[pos+1];
                if (kh==1 && kw==0){
                    // panel A ends at ci56: m0 full + m1 bits 0..23
                    c3_run(acc[i], wsm, kw, m0, 0, lane);
                    c3_run(acc[i], wsm, kw, m1 & 0x00FFFFFFu, 32, lane);
                    tot[i].x = add2(tot[i].x, acc[i].x);
                    tot[i].y = add2(tot[i].y, acc[i].y);
                    acc[i] = make_ulonglong2(0ULL,0ULL);
                    c3_run(acc[i], wsm, kw, m1 & 0xFF000000u, 32, lane);
                } else if (kh==2 && kw==1){
                    // panel B ends at ci48: m0 full + m1 bits 0..15
                    c3_run(acc[i], wsm, kw, m0, 0, lane);
                    c3_run(acc[i], wsm, kw, m1 & 0x0000FFFFu, 32, lane);
                    tot[i].x = add2(tot[i].x, acc[i].x);
                    tot[i].y = add2(tot[i].y, acc[i].y);
                    acc[i] = make_ulonglong2(0ULL,0ULL);
                    c3_run(acc[i], wsm, kw, m1 & 0xFFFF0000u, 32, lane);
                } else {
                    c3_run(acc[i], wsm, kw, m0, 0, lane);
                    c3_run(acc[i], wsm, kw, m1, 32, lane);
                }
            }
        }
    }
    float4* opb = (float4*)(g_buf5 + (size_t)t*32768 + b*8192);
    #pragma unroll
    for (int i=0;i<4;i++){
        int px = warp*4 + i;
        tot[i].x = add2(tot[i].x, acc[i].x);
        tot[i].y = add2(tot[i].y, acc[i].y);
        opb[px*32 + lane] = *reinterpret_cast<float4*>(&tot[i]);
    }
}

// ---------------- dense1: 2048 -> 256. K = 8x248 + 64 panels -------------------
__global__ void dense1_kernel(){
    __shared__ float xs[8][KC];
    int row0 = blockIdx.x*8;
    int o = threadIdx.x;
    float acc[8], tot[8];
    #pragma unroll
    for (int r=0;r<8;r++){ acc[r]=0.f; tot[r]=0.f; }
    int k0 = 0;
    for (int p=0; p<9; p++){
        int L = (p<8) ? KC : (2048 - 8*KC);
        __syncthreads();
        for (int i=threadIdx.x; i<8*L; i+=256){
            int r = i / L, kk = i - r*L;
            int k = k0 + kk;
            int c = k >> 4, hw = k & 15;
            xs[r][kk] = g_buf6[(size_t)(row0+r)*2048 + hw*128 + c];
        }
        __syncthreads();
        for (int kk=0; kk<L; kk++){
            float wv = g_w4at[(size_t)(k0+kk)*256 + o];
            #pragma unroll
            for (int r=0;r<8;r++) acc[r] = __fmaf_rn(xs[r][kk], wv, acc[r]);
        }
        #pragma unroll
        for (int r=0;r<8;r++){ tot[r] = __fadd_rn(tot[r], acc[r]); acc[r]=0.f; }
        k0 += L;
    }
    for (int r=0;r<8;r++) g_buf7[(size_t)(row0+r)*256 + o] = tot[r];
}

// ---------------- dense2: 256 -> 11. K = 248 + 8 panels ------------------------
__global__ void dense2_kernel(const float* __restrict__ w4b){
    int tb = blockIdx.x;
    __shared__ float xs[256];
    int tid = threadIdx.x;
    for (int i=tid;i<256;i+=64) xs[i] = g_buf7[(size_t)tb*256 + i];
    __syncthreads();
    if (tid < 11){
        float acc = 0.f;
        for (int k=0;k<KC;k++)  acc = __fmaf_rn(xs[k], w4b[tid*256+k], acc);
        float tot = acc; acc = 0.f;
        for (int k=KC;k<256;k++) acc = __fmaf_rn(xs[k], w4b[tid*256+k], acc);
        tot = __fadd_rn(tot, acc);
        int t = tb >> 2, b = tb & 3;
        g_buf8[t*44 + b*11 + tid] = tot;
    }
}

// ---------------- final scan, output layout [b][o][t] --------------------------
__global__ void scan_out_kernel(float* __restrict__ out){
    int n = threadIdx.x;
    if (n >= 44) return;
    int b = n/11, o = n - b*11;
    float s1=0.f, s2=0.f, r1=0.f, r2=0.f;
    #pragma unroll 4
    for (int t=0;t<TT;t++){
        float x = g_buf8[t*44 + n];
        s2 = __fmul_rn(DCAY, __fadd_rn(s2, s1));
        s1 = __fadd_rn(__fmul_rn(DCAY, s1), x);
        r2 = __fmul_rn(DCAY, __fadd_rn(r2, r1));
        r1 = __fmul_rn(DCAY, r1);
        float u = __fmul_rn(PSPS, s2);
        float v = __fsub_rn(__fsub_rn(u, __fmul_rn(REFS, r2)), THR);
        float spk = (v >= 0.f) ? 1.f : 0.f;
        r1 = __fadd_rn(r1, spk);
        out[(size_t)(b*11+o)*TT + t] = spk;
    }
}

extern "C" void kernel_launch(void* const* d_in, const int* in_sizes, int n_in,
                              void* d_out, int out_size){
    const float* s_in = (const float*)d_in[0];
    const float* w1   = (const float*)d_in[1];
    const float* w2   = (const float*)d_in[2];
    const float* w3   = (const float*)d_in[3];
    const float* w4a  = (const float*)d_in[4];
    const float* w4b  = (const float*)d_in[5];
    float* out = (float*)d_out;

    float *b0,*b1,*b2,*b3,*b4,*b5,*b6,*b7;
    cudaGetSymbolAddress((void**)&b0, g_buf0);
    cudaGetSymbolAddress((void**)&b1, g_buf1);
    cudaGetSymbolAddress((void**)&b2, g_buf2);
    cudaGetSymbolAddress((void**)&b3, g_buf3);
    cudaGetSymbolAddress((void**)&b4, g_buf4);
    cudaGetSymbolAddress((void**)&b5, g_buf5);
    cudaGetSymbolAddress((void**)&b6, g_buf6);
    cudaGetSymbolAddress((void**)&b7, g_buf7);

    static bool attr_done = false;
    if (!attr_done){
        cudaFuncSetAttribute(conv2_kernel, cudaFuncAttributeMaxDynamicSharedMemorySize, 75072);
        cudaFuncSetAttribute(conv3_kernel, cudaFuncAttributeMaxDynamicSharedMemorySize, 99136);
        attr_done = true;
    }

    prep_all_k<<<2048,256>>>(w1, w2, w3, w4a);

    pool0_kernel<<<dim3(10,1024), dim3(32,8)>>>(s_in);
    scan_kernel<<<32,256>>>(b0, 8192);

    conv1_kernel<<<1200, 512>>>();
    scan2_pool_kernel<32,32><<<128,256>>>(b1, b2);

    conv2_kernel<<<1200, 512, 75072>>>();
    scan2_pool_kernel<64,16><<<64,256>>>(b3, b4);

    conv3_kernel<<<1200, 512, 99136>>>();
    scan2_pool_kernel<128,8><<<32,256>>>(b5, b6);

    dense1_kernel<<<150,256>>>();
    scan_kernel<<<4,256>>>(b7, 1024);

    dense2_kernel<<<1200,64>>>(w4b);
    scan_out_kernel<<<1,64>>>(out);
}

// round 17
// speedup vs baseline: 1.7084x; 1.0816x over previous
#include <cuda_runtime.h>

#define TT 300
#define NB 4

// f32-rounded versions of the reference's double constants
#define DCAY 0.8187307530779818f   // exp(-1/5)
#define PSPS 0.5436563656918091f   // e/5
#define REFS 1.3591409142295226f   // 2*1.25*e/5
#define THR  1.25f
#define PW   1.375f                // 1.1*theta (exact in f32)

#define KC 248                     // Eigen depth-panel size (ARM defaults)

typedef unsigned long long u64;

// ---- packed f32x2 helpers: per-lane rounding identical to scalar FFMA/FADD ----
__device__ __forceinline__ u64 pk2(float v){
    u64 r; asm("mov.b64 %0, {%1, %1};" : "=l"(r) : "f"(v)); return r;
}
__device__ __forceinline__ u64 fma2(u64 v, u64 w, u64 a){
    u64 r; asm("fma.rn.f32x2 %0, %1, %2, %3;" : "=l"(r) : "l"(v), "l"(w), "l"(a)); return r;
}
__device__ __forceinline__ u64 add2(u64 a, u64 b){
    u64 r; asm("add.rn.f32x2 %0, %1, %2;" : "=l"(r) : "l"(a), "l"(b)); return r;
}

// ---- scratch, time-major, CHANNEL-MINOR spatial layouts ----
__device__ float g_buf0[TT*8192];     // [t][4][32][32][2]
__device__ float g_buf1[TT*131072];   // [t][4][32][32][32]  conv1 raw
__device__ float g_buf2[TT*32768];    // [t][4][16][16][32]
__device__ float g_buf3[TT*65536];    // [t][4][16][16][64]  conv2 raw
__device__ float g_buf4[TT*16384];    // [t][4][8][8][64]
__device__ float g_buf5[TT*32768];    // [t][4][8][8][128]   conv3 raw
__device__ float g_buf6[TT*8192];     // [t][4][4][4][128]
__device__ float g_buf7[TT*1024];     // [t][4][256]
__device__ float g_buf8[TT*44];       // [t][4][11]

// weights transposed to [kh][kw][ci][oc] (HWIO): k-ascending == (kh,kw,ci), ci fastest
__device__ __align__(16) float g_w1t[50*32];
__device__ __align__(16) float g_w2t[288*64];
__device__ __align__(16) float g_w3t[576*128];
__device__ __align__(16) float g_w4at[2048*256];   // [k][o]

// ---------------- merged weight transpose (single launch) ----------------
__global__ void prep_all_k(const float* __restrict__ w1, const float* __restrict__ w2,
                           const float* __restrict__ w3, const float* __restrict__ w4a){
    int i = blockIdx.x*256 + threadIdx.x;
    if (i < 32*50){
        int o = i/50, rem = i%50;
        int c = rem/25, r = rem%25, kh = r/5, kw = r%5;
        g_w1t[((kh*5+kw)*2 + c)*32 + o] = w1[i];
    }
    if (i < 64*288){
        int o = i/288, rem = i%288;
        int ci = rem/9, r = rem%9, kh = r/3, kw = r%3;
        g_w2t[((kh*3+kw)*32 + ci)*64 + o] = w2[i];
    }
    if (i < 128*576){
        int o = i/576, rem = i%576;
        int ci = rem/9, r = rem%9, kh = r/3, kw = r%3;
        g_w3t[((kh*3+kw)*64 + ci)*128 + o] = w3[i];
    }
    if (i < 256*2048){
        int o = i/2048, k = i%2048;
        g_w4at[k*256+o] = w4a[i];
    }
}

// ---------------- stage 0: 4x4 sum-pool (binary inputs -> exact) ----------------
__global__ void pool0_kernel(const float* __restrict__ s){
    int t = blockIdx.x*32 + threadIdx.x;
    int n = blockIdx.y*blockDim.y + threadIdx.y;
    if (t >= TT) return;
    int c = n & 1, ow = (n>>1)&31, oh = (n>>6)&31, b = n>>11;
    const float* base = s + (size_t)(((b*2+c)*128 + oh*4)*128 + ow*4)*TT + t;
    float acc = 0.f;
    #pragma unroll
    for (int i=0;i<4;i++)
        #pragma unroll
        for (int j=0;j<4;j++)
            acc += base[(i*128+j)*TT];
    g_buf0[(size_t)t*8192 + n] = acc * PW;
}

// ---------------- fused PSP + refractory + threshold scan (strict rn) ----------
// depth-3 prefetch: loads are scan-state-independent.
__global__ void scan_kernel(float* __restrict__ buf, int N){
    int n = blockIdx.x*blockDim.x + threadIdx.x;
    if (n >= N) return;
    float s1=0.f, s2=0.f, r1=0.f, r2=0.f;
    float pf[3];
    pf[0] = buf[n];
    pf[1] = buf[n + (size_t)N];
    pf[2] = buf[n + 2*(size_t)N];
    size_t idx = n;
    #pragma unroll 3
    for (int t=0; t<TT; t++, idx += N){
        int slot = t % 3;
        float x = pf[slot];
        pf[slot] = (t+3 < TT) ? buf[idx + 3*(size_t)N] : 0.f;
        s2 = __fmul_rn(DCAY, __fadd_rn(s2, s1));
        s1 = __fadd_rn(__fmul_rn(DCAY, s1), x);
        r2 = __fmul_rn(DCAY, __fadd_rn(r2, r1));
        r1 = __fmul_rn(DCAY, r1);
        float u = __fmul_rn(PSPS, s2);
        float v = __fsub_rn(__fsub_rn(u, __fmul_rn(REFS, r2)), THR);
        float spk = (v >= 0.f) ? 1.f : 0.f;
        r1 = __fadd_rn(r1, spk);
        buf[idx] = spk;
    }
}

// ---------------- fused: scan(conv raw) -> 2x2 pool -> scan(pooled) ------------
// Bit-identical to scan + pool + scan chain. depth-3 prefetch.
template<int C, int Hin>
__global__ void scan2_pool_kernel(const float* __restrict__ in, float* __restrict__ out){
    const int Ho = Hin/2;
    const int Npool = 4*C*Ho*Ho;
    const int Tin = 4*C*Hin*Hin;
    int n = blockIdx.x*256 + threadIdx.x;
    int c = n & (C-1);
    int r = n / C;
    int ow = r % Ho; r /= Ho;
    int oh = r % Ho;
    int b = r / Ho;
    size_t base = ((size_t)(b*Hin + 2*oh)*Hin + 2*ow)*C + c;
    float S1[4]={0,0,0,0}, S2[4]={0,0,0,0}, R1[4]={0,0,0,0}, R2[4]={0,0,0,0};
    float ps1=0.f, ps2=0.f, pr1=0.f, pr2=0.f;
    const int off1 = C, off2 = Hin*C, off3 = Hin*C + C;
    float pf[3][4];
    #pragma unroll
    for (int d=0;d<3;d++){
        const float* p = in + (size_t)d*Tin + base;
        pf[d][0]=p[0]; pf[d][1]=p[off1]; pf[d][2]=p[off2]; pf[d][3]=p[off3];
    }
    #pragma unroll 3
    for (int t=0; t<TT; t++){
        int slot = t % 3;
        float xs[4] = {pf[slot][0], pf[slot][1], pf[slot][2], pf[slot][3]};
        if (t+3 < TT){
            const float* pn = in + (size_t)(t+3)*Tin + base;
            pf[slot][0]=pn[0]; pf[slot][1]=pn[off1]; pf[slot][2]=pn[off2]; pf[slot][3]=pn[off3];
        }
        float sum = 0.f;
        #pragma unroll
        for (int j=0;j<4;j++){
            S2[j] = __fmul_rn(DCAY, __fadd_rn(S2[j], S1[j]));
            S1[j] = __fadd_rn(__fmul_rn(DCAY, S1[j]), xs[j]);
            R2[j] = __fmul_rn(DCAY, __fadd_rn(R2[j], R1[j]));
            R1[j] = __fmul_rn(DCAY, R1[j]);
            float u = __fmul_rn(PSPS, S2[j]);
            float v = __fsub_rn(__fsub_rn(u, __fmul_rn(REFS, R2[j])), THR);
            float spk = (v >= 0.f) ? 1.f : 0.f;
            R1[j] = __fadd_rn(R1[j], spk);
            sum += spk;                         // exact: small integers
        }
        float x = sum * PW;                     // exact
        ps2 = __fmul_rn(DCAY, __fadd_rn(ps2, ps1));
        ps1 = __fadd_rn(__fmul_rn(DCAY, ps1), x);
        pr2 = __fmul_rn(DCAY, __fadd_rn(pr2, pr1));
        pr1 = __fmul_rn(DCAY, pr1);
        float u = __fmul_rn(PSPS, ps2);
        float v = __fsub_rn(__fsub_rn(u, __fmul_rn(REFS, pr2)), THR);
        float spk = (v >= 0.f) ? 1.f : 0.f;
        pr1 = __fadd_rn(pr1, spk);
        out[(size_t)t*Npool + n] = spk;
    }
}

// ---------------- conv1 (DENSE f32x2): 2->32, 5x5 pad2, 32x32 ------------------
// block (32,8,2), 2 blocks/SM. Each thread: 2 row-groups x 2 og-subgroups of
// (2 px x 8 oc) sequentially -> only 8 u64 accumulators live. Measured 153.6us.
__global__ void __launch_bounds__(512,2) conv1_kernel(){
    int tb = blockIdx.x; int b = tb & 3; int t = tb >> 2;
    __shared__ float tile[36*36*2];
    __shared__ __align__(16) float ws[50*32];
    int tx = threadIdx.x, ty = threadIdx.y, tz = threadIdx.z;
    int tid = (tz*8 + ty)*32 + tx;          // 0..511
    const float* inp = g_buf0 + (size_t)t*8192 + b*2048;
    for (int i = tid; i < 36*36*2; i += 512){
        int c = i & 1; int xy = i >> 1; int x = xy % 36; int y = xy / 36;
        int h = y-2, w = x-2;
        float v = 0.f;
        if ((unsigned)h < 32u && (unsigned)w < 32u) v = inp[(h*32+w)*2 + c];
        tile[i] = v;
    }
    for (int i = tid; i < 400; i += 512) ((float4*)ws)[i] = ((const float4*)g_w1t)[i];
    __syncthreads();
    int ox = tx;
    const u64* ws64 = (const u64*)ws;
    for (int s = 0; s < 2; s++){
        int oyA = ty + 16*s;                // pixel rows oyA, oyA+8
        for (int g = 0; g < 2; g++){        // oc base = tz*16 + g*8 -> u64 off tz*8+g*4
            int wo = tz*8 + g*4;
            u64 aA[4], aB[4];
            #pragma unroll
            for (int i=0;i<4;i++){ aA[i]=0ULL; aB[i]=0ULL; }
            for (int kh=0;kh<5;kh++)
                #pragma unroll
                for (int kw=0;kw<5;kw++){
                    float2 vA2 = *(const float2*)(tile + ((oyA+kh)*36 + ox+kw)*2);
                    float2 vB2 = *(const float2*)(tile + ((oyA+8+kh)*36 + ox+kw)*2);
                    u64 vA0=pk2(vA2.x), vA1=pk2(vA2.y), vB0=pk2(vB2.x), vB1=pk2(vB2.y);
                    const ulonglong2* w0 = (const ulonglong2*)(ws64 + ((kh*5+kw)*2+0)*16 + wo);
                    const ulonglong2* w1 = (const ulonglong2*)(ws64 + ((kh*5+kw)*2+1)*16 + wo);
                    #pragma unroll
                    for (int q=0;q<2;q++){
                        ulonglong2 wc0 = w0[q];
                        ulonglong2 wc1 = w1[q];
                        aA[2*q]   = fma2(vA0, wc0.x, aA[2*q]);
                        aA[2*q+1] = fma2(vA0, wc0.y, aA[2*q+1]);
                        aB[2*q]   = fma2(vB0, wc0.x, aB[2*q]);
                        aB[2*q+1] = fma2(vB0, wc0.y, aB[2*q+1]);
                        aA[2*q]   = fma2(vA1, wc1.x, aA[2*q]);
                        aA[2*q+1] = fma2(vA1, wc1.y, aA[2*q+1]);
                        aB[2*q]   = fma2(vB1, wc1.x, aB[2*q]);
                        aB[2*q+1] = fma2(vB1, wc1.y, aB[2*q+1]);
                    }
                }
            float2* opA = (float2*)(g_buf1 + (size_t)t*131072 + b*32768 + (oyA*32+ox)*32 + tz*16 + g*8);
            float2* opB = (float2*)(g_buf1 + (size_t)t*131072 + b*32768 + ((oyA+8)*32+ox)*32 + tz*16 + g*8);
            #pragma unroll
            for (int q=0;q<4;q++){ opA[q] = *reinterpret_cast<float2*>(&aA[q]);
                                   opB[q] = *reinterpret_cast<float2*>(&aB[q]); }
        }
    }
}

// ================= SPARSE CONVS (conv2/conv3) =================
// All conv inputs are binary spikes. fma(0,w,acc)=acc and fma(1,w,acc)=fadd(acc,w)
// bit-exactly, so summing weight rows over active taps in the same ascending
// k-order with the same panel splits reproduces the dense chain bit-for-bit.
// One warp per pixel: activity mask is warp-uniform -> no divergence.

// ---------------- conv2: 32->64, 3x3 pad1, 16x16. K=288 = 248 + 40 ------------
// Panel boundary k=248 -> tap7 ci24. Lane owns oc pair {2l,2l+1} (1 u64).
extern __shared__ float s_dyn[];
__global__ void __launch_bounds__(512,2) conv2_kernel(){
    int tb = blockIdx.x; int b = tb & 3; int t = tb >> 2;
    u64* wsm = (u64*)s_dyn;                          // [288 rows][32 u64] = 73728 B
    unsigned* msk = (unsigned*)(s_dyn + 18432);      // 324 u32
    int tid = threadIdx.x; int lane = tid & 31; int warp = tid >> 5;
    const float* inp = g_buf2 + (size_t)t*32768 + b*8192;
    for (int i = tid; i < 4608; i += 512) ((float4*)wsm)[i] = ((const float4*)g_w2t)[i];
    for (int pos = warp; pos < 324; pos += 16){
        int x = pos % 18, y = pos / 18, h = y-1, w = x-1;
        float v = 0.f;
        if ((unsigned)h < 16u && (unsigned)w < 16u) v = inp[(h*16+w)*32 + lane];
        unsigned m = __ballot_sync(0xffffffffu, v != 0.f);
        if (lane == 0) msk[pos] = m;
    }
    __syncthreads();
    float2* opb = (float2*)(g_buf3 + (size_t)t*65536 + b*16384);
    for (int i = 0; i < 16; i++){
        int px = warp*16 + i;
        int ox = px & 15, oy = px >> 4;
        u64 acc = 0ULL;
        // panel A: taps 0..6 full + tap7 ci<24
        #pragma unroll
        for (int tap=0; tap<7; tap++){
            unsigned m = msk[(oy + tap/3)*18 + ox + tap%3];
            const u64* wrow = wsm + tap*1024;
            while (m){ int ci = __ffs(m)-1; m &= m-1;
                       acc = add2(acc, wrow[ci*32 + lane]); }
        }
        unsigned m7 = msk[(oy+2)*18 + ox+1];
        {   unsigned m = m7 & 0x00FFFFFFu;
            const u64* wrow = wsm + 7*1024;
            while (m){ int ci = __ffs(m)-1; m &= m-1;
                       acc = add2(acc, wrow[ci*32 + lane]); }
        }
        u64 tot = acc; acc = 0ULL;
        // panel B: tap7 ci>=24 + tap8 full
        {   unsigned m = m7 & 0xFF000000u;
            const u64* wrow = wsm + 7*1024;
            while (m){ int ci = __ffs(m)-1; m &= m-1;
                       acc = add2(acc, wrow[ci*32 + lane]); }
        }
        {   unsigned m = msk[(oy+2)*18 + ox+2];
            const u64* wrow = wsm + 8*1024;
            while (m){ int ci = __ffs(m)-1; m &= m-1;
                       acc = add2(acc, wrow[ci*32 + lane]); }
        }
        acc = add2(tot, acc);                    // single panel-combine fadd
        opb[px*32 + lane] = *reinterpret_cast<float2*>(&acc);
    }
}

// ---------------- conv3: 64->128, 3x3 pad1, 8x8. K=576 = 248+248+80 -----------
// Boundaries: k=248 (tap3 ci56), k=496 (tap7 ci48). Lane owns oc {4l..4l+3}
// (ulonglong2). Weights staged per kh (98.3 KB); 4 px per warp, accs persist.
__device__ __forceinline__ void c3_run(ulonglong2& acc, const u64* wsm,
                                       int kw, unsigned m, int cibase, int lane){
    const u64* wrow0 = wsm + kw*4096 + 2*lane;
    while (m){
        int bit = __ffs(m)-1; m &= m-1;
        const ulonglong2 w = *(const ulonglong2*)(wrow0 + (cibase + bit)*64);
        acc.x = add2(acc.x, w.x);
        acc.y = add2(acc.y, w.y);
    }
}
__global__ void __launch_bounds__(512,2) conv3_kernel(){
    int tb = blockIdx.x; int b = tb & 3; int t = tb >> 2;
    u64* wsm = (u64*)s_dyn;                          // per-kh [3 kw][64 ci][64 u64] = 98304 B
    unsigned* msk = (unsigned*)(s_dyn + 24576);      // [100][2] u32
    int tid = threadIdx.x; int lane = tid & 31; int warp = tid >> 5;
    const float* inp = g_buf4 + (size_t)t*16384 + b*4096;
    for (int pos = warp; pos < 100; pos += 16){
        int x = pos % 10, y = pos / 10, h = y-1, w = x-1;
        float v0 = 0.f, v1 = 0.f;
        if ((unsigned)h < 8u && (unsigned)w < 8u){
            const float* p = inp + (h*8+w)*64;
            v0 = p[lane]; v1 = p[32 + lane];
        }
        unsigned m0 = __ballot_sync(0xffffffffu, v0 != 0.f);
        unsigned m1 = __ballot_sync(0xffffffffu, v1 != 0.f);
        if (lane == 0){ msk[pos*2] = m0; msk[pos*2+1] = m1; }
    }
    ulonglong2 acc[4], tot[4];
    #pragma unroll
    for (int i=0;i<4;i++){ acc[i] = make_ulonglong2(0ULL,0ULL); tot[i] = make_ulonglong2(0ULL,0ULL); }
    for (int kh=0; kh<3; kh++){
        __syncthreads();
        for (int i = tid; i < 6144; i += 512){       // 192 rows x 32 float4
            int f4 = i & 31; int row = i >> 5;
            ((float4*)wsm)[i] = ((const float4*)g_w3t)[(kh*192 + row)*32 + f4];
        }
        __syncthreads();
        #pragma unroll
        for (int i=0;i<4;i++){
            int px = warp*4 + i;
            int ox = px & 7, oy = px >> 3;
            #pragma unroll
            for (int kw=0;kw<3;kw++){
                int pos = ((oy+kh)*10 + ox+kw)*2;
                unsigned m0 = msk[pos], m1 = msk[pos+1];
                if (kh==1 && kw==0){
                    // panel A ends at ci56: m0 full + m1 bits 0..23
                    c3_run(acc[i], wsm, kw, m0, 0, lane);
                    c3_run(acc[i], wsm, kw, m1 & 0x00FFFFFFu, 32, lane);
                    tot[i].x = add2(tot[i].x, acc[i].x);
                    tot[i].y = add2(tot[i].y, acc[i].y);
                    acc[i] = make_ulonglong2(0ULL,0ULL);
                    c3_run(acc[i], wsm, kw, m1 & 0xFF000000u, 32, lane);
                } else if (kh==2 && kw==1){
                    // panel B ends at ci48: m0 full + m1 bits 0..15
                    c3_run(acc[i], wsm, kw, m0, 0, lane);
                    c3_run(acc[i], wsm, kw, m1 & 0x0000FFFFu, 32, lane);
                    tot[i].x = add2(tot[i].x, acc[i].x);
                    tot[i].y = add2(tot[i].y, acc[i].y);
                    acc[i] = make_ulonglong2(0ULL,0ULL);
                    c3_run(acc[i], wsm, kw, m1 & 0xFFFF0000u, 32, lane);
                } else {
                    c3_run(acc[i], wsm, kw, m0, 0, lane);
                    c3_run(acc[i], wsm, kw, m1, 32, lane);
                }
            }
        }
    }
    float4* opb = (float4*)(g_buf5 + (size_t)t*32768 + b*8192);
    #pragma unroll
    for (int i=0;i<4;i++){
        int px = warp*4 + i;
        tot[i].x = add2(tot[i].x, acc[i].x);
        tot[i].y = add2(tot[i].y, acc[i].y);
        opb[px*32 + lane] = *reinterpret_cast<float4*>(&tot[i]);
    }
}

// ---------------- dense1: 2048 -> 256. K = 8x248 + 64 panels -------------------
__global__ void dense1_kernel(){
    __shared__ float xs[8][KC];
    int row0 = blockIdx.x*8;
    int o = threadIdx.x;
    float acc[8], tot[8];
    #pragma unroll
    for (int r=0;r<8;r++){ acc[r]=0.f; tot[r]=0.f; }
    int k0 = 0;
    for (int p=0; p<9; p++){
        int L = (p<8) ? KC : (2048 - 8*KC);
        __syncthreads();
        for (int i=threadIdx.x; i<8*L; i+=256){
            int r = i / L, kk = i - r*L;
            int k = k0 + kk;
            int c = k >> 4, hw = k & 15;
            xs[r][kk] = g_buf6[(size_t)(row0+r)*2048 + hw*128 + c];
        }
        __syncthreads();
        for (int kk=0; kk<L; kk++){
            float wv = g_w4at[(size_t)(k0+kk)*256 + o];
            #pragma unroll
            for (int r=0;r<8;r++) acc[r] = __fmaf_rn(xs[r][kk], wv, acc[r]);
        }
        #pragma unroll
        for (int r=0;r<8;r++){ tot[r] = __fadd_rn(tot[r], acc[r]); acc[r]=0.f; }
        k0 += L;
    }
    for (int r=0;r<8;r++) g_buf7[(size_t)(row0+r)*256 + o] = tot[r];
}

// ---------------- dense2: 256 -> 11. K = 248 + 8 panels ------------------------
__global__ void dense2_kernel(const float* __restrict__ w4b){
    int tb = blockIdx.x;
    __shared__ float xs[256];
    int tid = threadIdx.x;
    for (int i=tid;i<256;i+=64) xs[i] = g_buf7[(size_t)tb*256 + i];
    __syncthreads();
    if (tid < 11){
        float acc = 0.f;
        for (int k=0;k<KC;k++)  acc = __fmaf_rn(xs[k], w4b[tid*256+k], acc);
        float tot = acc; acc = 0.f;
        for (int k=KC;k<256;k++) acc = __fmaf_rn(xs[k], w4b[tid*256+k], acc);
        tot = __fadd_rn(tot, acc);
        int t = tb >> 2, b = tb & 3;
        g_buf8[t*44 + b*11 + tid] = tot;
    }
}

// ---------------- final scan, output layout [b][o][t] --------------------------
__global__ void scan_out_kernel(float* __restrict__ out){
    int n = threadIdx.x;
    if (n >= 44) return;
    int b = n/11, o = n - b*11;
    float s1=0.f, s2=0.f, r1=0.f, r2=0.f;
    #pragma unroll 4
    for (int t=0;t<TT;t++){
        float x = g_buf8[t*44 + n];
        s2 = __fmul_rn(DCAY, __fadd_rn(s2, s1));
        s1 = __fadd_rn(__fmul_rn(DCAY, s1), x);
        r2 = __fmul_rn(DCAY, __fadd_rn(r2, r1));
        r1 = __fmul_rn(DCAY, r1);
        float u = __fmul_rn(PSPS, s2);
        float v = __fsub_rn(__fsub_rn(u, __fmul_rn(REFS, r2)), THR);
        float spk = (v >= 0.f) ? 1.f : 0.f;
        r1 = __fadd_rn(r1, spk);
        out[(size_t)(b*11+o)*TT + t] = spk;
    }
}

extern "C" void kernel_launch(void* const* d_in, const int* in_sizes, int n_in,
                              void* d_out, int out_size){
    const float* s_in = (const float*)d_in[0];
    const float* w1   = (const float*)d_in[1];
    const float* w2   = (const float*)d_in[2];
    const float* w3   = (const float*)d_in[3];
    const float* w4a  = (const float*)d_in[4];
    const float* w4b  = (const float*)d_in[5];
    float* out = (float*)d_out;

    float *b0,*b1,*b2,*b3,*b4,*b5,*b6,*b7;
    cudaGetSymbolAddress((void**)&b0, g_buf0);
    cudaGetSymbolAddress((void**)&b1, g_buf1);
    cudaGetSymbolAddress((void**)&b2, g_buf2);
    cudaGetSymbolAddress((void**)&b3, g_buf3);
    cudaGetSymbolAddress((void**)&b4, g_buf4);
    cudaGetSymbolAddress((void**)&b5, g_buf5);
    cudaGetSymbolAddress((void**)&b6, g_buf6);
    cudaGetSymbolAddress((void**)&b7, g_buf7);

    static bool attr_done = false;
    if (!attr_done){
        cudaFuncSetAttribute(conv2_kernel, cudaFuncAttributeMaxDynamicSharedMemorySize, 75072);
        cudaFuncSetAttribute(conv3_kernel, cudaFuncAttributeMaxDynamicSharedMemorySize, 99136);
        attr_done = true;
    }

    prep_all_k<<<2048,256>>>(w1, w2, w3, w4a);

    pool0_kernel<<<dim3(10,1024), dim3(32,8)>>>(s_in);
    scan_kernel<<<32,256>>>(b0, 8192);

    conv1_kernel<<<1200, dim3(32,8,2)>>>();
    scan2_pool_kernel<32,32><<<128,256>>>(b1, b2);

    conv2_kernel<<<1200, 512, 75072>>>();
    scan2_pool_kernel<64,16><<<64,256>>>(b3, b4);

    conv3_kernel<<<1200, 512, 99136>>>();
    scan2_pool_kernel<128,8><<<32,256>>>(b5, b6);

    dense1_kernel<<<150,256>>>();
    scan_kernel<<<4,256>>>(b7, 1024);

    dense2_kernel<<<1200,64>>>(w4b);
    scan_out_kernel<<<1,64>>>(out);
}